// round 8
// baseline (speedup 1.0000x reference)
#include <cuda_runtime.h>
#include <cuda_fp16.h>

#define NMAX 50000
#define EMAX 800000
#define FEAT 64
#define OUTF 16
#define SCAN_BS 256

// Scratch (zero-initialized at load; gather2 re-zeroes counters each replay)
__device__ __half g_h1[NMAX * FEAT];    // (X@W1) * norm_src, fp16
__device__ __half g_h2[NMAX * OUTF];    // (out1@W2) * norm_src, fp16
__device__ int    g_deg_src[NMAX];
__device__ int    g_deg_dst[NMAX];
__device__ int    g_cnt[NMAX];
__device__ int    g_scan[NMAX];         // intra-block exclusive scan of deg_dst
__device__ int    g_bsum[SCAN_BS];      // raw per-block sums
__device__ int    g_bsum_s[SCAN_BS];    // exclusive-scanned block sums
__device__ int    g_done;               // scanA completion ticket
__device__ int    g_csr_src[EMAX];      // src ids grouped by dst

__device__ __forceinline__ float deg_norm(int d) {
    return rsqrtf(fmaxf((float)d, 1.0f));
}

// ---------------- degree count: 4 edges/thread ----------------
__global__ void count_deg_kernel(const int* __restrict__ src,
                                 const int* __restrict__ dst, int e) {
    int i = blockIdx.x * blockDim.x + threadIdx.x;
    int e4 = e >> 2;
    if (i < e4) {
        int4 s = __ldg((const int4*)src + i);
        int4 d = __ldg((const int4*)dst + i);
        atomicAdd(&g_deg_src[s.x], 1);
        atomicAdd(&g_deg_src[s.y], 1);
        atomicAdd(&g_deg_src[s.z], 1);
        atomicAdd(&g_deg_src[s.w], 1);
        atomicAdd(&g_deg_dst[d.x], 1);
        atomicAdd(&g_deg_dst[d.y], 1);
        atomicAdd(&g_deg_dst[d.z], 1);
        atomicAdd(&g_deg_dst[d.w], 1);
    }
    if (i == 0) {
        for (int j = e4 << 2; j < e; j++) {
            atomicAdd(&g_deg_src[__ldg(&src[j])], 1);
            atomicAdd(&g_deg_dst[__ldg(&dst[j])], 1);
        }
    }
}

// ---------------- scan A: block scan of deg_dst; last block scans bsum ----------------
__global__ void scanA_kernel(int n) {
    int t = threadIdx.x;
    int i = blockIdx.x * SCAN_BS + t;
    int v = (i < n) ? g_deg_dst[i] : 0;
    int lane = t & 31, w = t >> 5;
    int incl = v;
#pragma unroll
    for (int d = 1; d < 32; d <<= 1) {
        int x = __shfl_up_sync(0xffffffffu, incl, d);
        if (lane >= d) incl += x;
    }
    __shared__ int wsum[8];
    if (lane == 31) wsum[w] = incl;
    __syncthreads();
    if (w == 0) {
        int s = (lane < 8) ? wsum[lane] : 0;
#pragma unroll
        for (int d = 1; d < 8; d <<= 1) {
            int x = __shfl_up_sync(0xffffffffu, s, d);
            if (lane >= d) s += x;
        }
        if (lane < 8) wsum[lane] = s;
    }
    __syncthreads();
    int excl = incl - v + (w > 0 ? wsum[w - 1] : 0);
    if (i < n) g_scan[i] = excl;
    if (t == SCAN_BS - 1) g_bsum[blockIdx.x] = excl + v;

    __threadfence();
    __syncthreads();
    __shared__ int amLast;
    if (t == 0) amLast = (atomicAdd(&g_done, 1) == (int)gridDim.x - 1);
    __syncthreads();
    if (amLast) {
        int nb = gridDim.x;
        if (t < 32) {
            int carry = 0;
            for (int base = 0; base < nb; base += 32) {
                int idx = base + t;
                int bv = (idx < nb) ? g_bsum[idx] : 0;
                int bi = bv;
#pragma unroll
                for (int d = 1; d < 32; d <<= 1) {
                    int x = __shfl_up_sync(0xffffffffu, bi, d);
                    if (t >= d) bi += x;
                }
                if (idx < nb) g_bsum_s[idx] = carry + bi - bv;
                carry += __shfl_sync(0xffffffffu, bi, 31);
            }
            if (t == 0) g_done = 0;
        }
    }
}

// ---------------- CSR fill: 4 edges/thread ----------------
__global__ void fill_kernel(const int* __restrict__ src,
                            const int* __restrict__ dst, int e) {
    int i = blockIdx.x * blockDim.x + threadIdx.x;
    int e4 = e >> 2;
    if (i < e4) {
        int4 s = __ldg((const int4*)src + i);
        int4 d = __ldg((const int4*)dst + i);
        int b0 = g_scan[d.x] + g_bsum_s[d.x >> 8];
        int b1 = g_scan[d.y] + g_bsum_s[d.y >> 8];
        int b2 = g_scan[d.z] + g_bsum_s[d.z >> 8];
        int b3 = g_scan[d.w] + g_bsum_s[d.w >> 8];
        int p0 = b0 + atomicAdd(&g_cnt[d.x], 1);
        int p1 = b1 + atomicAdd(&g_cnt[d.y], 1);
        int p2 = b2 + atomicAdd(&g_cnt[d.z], 1);
        int p3 = b3 + atomicAdd(&g_cnt[d.w], 1);
        g_csr_src[p0] = s.x;
        g_csr_src[p1] = s.y;
        g_csr_src[p2] = s.z;
        g_csr_src[p3] = s.w;
    }
    if (i == 0) {
        for (int j = e4 << 2; j < e; j++) {
            int d = __ldg(&dst[j]);
            int pos = g_scan[d] + g_bsum_s[d >> 8] + atomicAdd(&g_cnt[d], 1);
            g_csr_src[pos] = __ldg(&src[j]);
        }
    }
}

// ---------------- GEMM 1: h1 = (X @ W1) * norm_src -> fp16 ----------------
// Depends only on deg_src (norm computed inline) -> forks right after count_deg.
__global__ void gemm1_kernel(const float* __restrict__ x,
                             const float* __restrict__ w1, int n) {
    __shared__ float ws[FEAT * FEAT];
    int tid = threadIdx.x;
    for (int i = tid; i < FEAT * FEAT; i += blockDim.x) ws[i] = w1[i];
    __syncthreads();

    int warp = tid >> 5;
    int lane = tid & 31;
    int r0 = (blockIdx.x * 8 + warp) * 4;
    if (r0 >= n) return;
    int rmax = n - r0;

    float2 xq[4];
#pragma unroll
    for (int j = 0; j < 4; j++) {
        xq[j] = (j < rmax) ? __ldg((const float2*)(x + (r0 + j) * FEAT) + lane)
                           : make_float2(0.f, 0.f);
    }

    float2 acc[4];
#pragma unroll
    for (int j = 0; j < 4; j++) acc[j] = make_float2(0.f, 0.f);

    const float2* ws2 = (const float2*)ws;
#pragma unroll
    for (int k = 0; k < FEAT; k++) {
        float2 wv = ws2[k * 32 + lane];
#pragma unroll
        for (int j = 0; j < 4; j++) {
            float xv = __shfl_sync(0xffffffffu, (k & 1) ? xq[j].y : xq[j].x, k >> 1);
            acc[j].x = fmaf(xv, wv.x, acc[j].x);
            acc[j].y = fmaf(xv, wv.y, acc[j].y);
        }
    }

#pragma unroll
    for (int j = 0; j < 4; j++) {
        int r = r0 + j;
        if (r < n) {
            float s = deg_norm(g_deg_src[r]);
            ((half2*)g_h1)[r * 32 + lane] =
                __float22half2_rn(make_float2(acc[j].x * s, acc[j].y * s));
        }
    }
}

// ---------------- Gather 1 + finalize + relu + fused GEMM2 ----------------
__global__ void gather1_kernel(const float* __restrict__ b1,
                               const float* __restrict__ w2, int n) {
    __shared__ float ws[FEAT * OUTF];
    int tid = threadIdx.x;
    for (int i = tid; i < FEAT * OUTF; i += blockDim.x) ws[i] = w2[i];
    __syncthreads();

    int warp = tid >> 5;
    int lane = tid & 31;
    int node = blockIdx.x * 8 + warp;
    if (node >= n) return;

    int beg = g_scan[node] + g_bsum_s[node >> 8];
    int deg = g_deg_dst[node];
    int end = beg + deg;
    const half2* h1v = (const half2*)g_h1;

    float2 acc = make_float2(0.f, 0.f);
    int j = beg;
    for (; j + 8 <= end; j += 8) {
        int s0 = __ldg(&g_csr_src[j]);
        int s1 = __ldg(&g_csr_src[j + 1]);
        int s2 = __ldg(&g_csr_src[j + 2]);
        int s3 = __ldg(&g_csr_src[j + 3]);
        int s4 = __ldg(&g_csr_src[j + 4]);
        int s5 = __ldg(&g_csr_src[j + 5]);
        int s6 = __ldg(&g_csr_src[j + 6]);
        int s7 = __ldg(&g_csr_src[j + 7]);
        float2 v0 = __half22float2(__ldg(h1v + s0 * 32 + lane));
        float2 v1 = __half22float2(__ldg(h1v + s1 * 32 + lane));
        float2 v2 = __half22float2(__ldg(h1v + s2 * 32 + lane));
        float2 v3 = __half22float2(__ldg(h1v + s3 * 32 + lane));
        float2 v4 = __half22float2(__ldg(h1v + s4 * 32 + lane));
        float2 v5 = __half22float2(__ldg(h1v + s5 * 32 + lane));
        float2 v6 = __half22float2(__ldg(h1v + s6 * 32 + lane));
        float2 v7 = __half22float2(__ldg(h1v + s7 * 32 + lane));
        acc.x += ((v0.x + v1.x) + (v2.x + v3.x)) + ((v4.x + v5.x) + (v6.x + v7.x));
        acc.y += ((v0.y + v1.y) + (v2.y + v3.y)) + ((v4.y + v5.y) + (v6.y + v7.y));
    }
    for (; j + 2 <= end; j += 2) {
        int s0 = __ldg(&g_csr_src[j]);
        int s1 = __ldg(&g_csr_src[j + 1]);
        float2 v0 = __half22float2(__ldg(h1v + s0 * 32 + lane));
        float2 v1 = __half22float2(__ldg(h1v + s1 * 32 + lane));
        acc.x += v0.x + v1.x;
        acc.y += v0.y + v1.y;
    }
    if (j < end) {
        int s = __ldg(&g_csr_src[j]);
        float2 v = __half22float2(__ldg(h1v + s * 32 + lane));
        acc.x += v.x;
        acc.y += v.y;
    }

    float nd = deg_norm(deg);
    float2 bb = __ldg((const float2*)b1 + lane);
    float2 o;                                    // out1 row in registers
    o.x = fmaxf(fmaf(acc.x, nd, bb.x), 0.f);
    o.y = fmaxf(fmaf(acc.y, nd, bb.y), 0.f);

    // fused GEMM2: lanes 0-15 cover k=0..31, lanes 16-31 cover k=32..63
    int c = lane & 15;
    int hf = lane >> 4;
    float a2 = 0.f;
#pragma unroll
    for (int kk = 0; kk < 32; kk++) {
        int k = hf * 32 + kk;
        float xv = __shfl_sync(0xffffffffu, (k & 1) ? o.y : o.x, k >> 1);
        a2 = fmaf(xv, ws[k * OUTF + c], a2);
    }
    a2 += __shfl_xor_sync(0xffffffffu, a2, 16);
    if (lane < 16) {
        g_h2[node * OUTF + lane] = __float2half(a2 * deg_norm(g_deg_src[node]));
    }
}

// ---------------- Gather 2 + finalize -> out; resets counters ----------------
__global__ void gather2_kernel(float* __restrict__ out,
                               const float* __restrict__ b2, int n) {
    int warp = threadIdx.x >> 5;
    int lane = threadIdx.x & 31;
    int node = blockIdx.x * 8 + warp;
    if (node >= n) return;

    int beg = g_scan[node] + g_bsum_s[node >> 8];
    int deg = g_deg_dst[node];
    int end = beg + deg;
    int f = lane & 15;
    int par = lane >> 4;

    float acc = 0.f;
    int j = beg + par;
    for (; j + 6 < end; j += 8) {
        int s0 = __ldg(&g_csr_src[j]);
        int s1 = __ldg(&g_csr_src[j + 2]);
        int s2 = __ldg(&g_csr_src[j + 4]);
        int s3 = __ldg(&g_csr_src[j + 6]);
        float a0 = __half2float(__ldg(&g_h2[s0 * OUTF + f]));
        float a1 = __half2float(__ldg(&g_h2[s1 * OUTF + f]));
        float a2 = __half2float(__ldg(&g_h2[s2 * OUTF + f]));
        float a3 = __half2float(__ldg(&g_h2[s3 * OUTF + f]));
        acc += (a0 + a1) + (a2 + a3);
    }
    for (; j < end; j += 2) {
        int s = __ldg(&g_csr_src[j]);
        acc += __half2float(__ldg(&g_h2[s * OUTF + f]));
    }

    acc += __shfl_xor_sync(0xffffffffu, acc, 16);
    if (lane < 16) {
        out[node * OUTF + f] = fmaf(acc, deg_norm(deg), __ldg(&b2[f]));
    }

    // reset per-node state for the next replay (zero-init covers the first run)
    if (lane == 0) {
        g_deg_src[node] = 0;
        g_deg_dst[node] = 0;
        g_cnt[node] = 0;
    }
}

extern "C" void kernel_launch(void* const* d_in, const int* in_sizes, int n_in,
                              void* d_out, int out_size) {
    const float* features = (const float*)d_in[0];
    const int*   src      = (const int*)d_in[1];
    const int*   dst      = (const int*)d_in[2];
    const float* W1       = (const float*)d_in[3];
    const float* b1       = (const float*)d_in[4];
    const float* W2       = (const float*)d_in[5];
    const float* b2       = (const float*)d_in[6];
    float* out = (float*)d_out;

    int n = in_sizes[0] / FEAT;   // 50000
    int e = in_sizes[1];          // 800000

    const int T = 256;
    int nb = (n + SCAN_BS - 1) / SCAN_BS;   // 196
    int e4 = e >> 2;

    static cudaStream_t s2 = 0;
    static cudaEvent_t evA = 0, evB = 0;
    if (!s2) {
        cudaStreamCreateWithFlags(&s2, cudaStreamNonBlocking);
        cudaEventCreateWithFlags(&evA, cudaEventDisableTiming);
        cudaEventCreateWithFlags(&evB, cudaEventDisableTiming);
    }

    count_deg_kernel<<<(e4 + T - 1) / T, T>>>(src, dst, e);

    // fork: gemm1 depends only on deg_src; overlaps scanA + fill
    cudaEventRecord(evA, 0);
    cudaStreamWaitEvent(s2, evA, 0);
    gemm1_kernel<<<(n + 31) / 32, T, 0, s2>>>(features, W1, n);
    cudaEventRecord(evB, s2);

    scanA_kernel<<<nb, SCAN_BS>>>(n);
    fill_kernel<<<(e4 + T - 1) / T, T>>>(src, dst, e);

    // join: gather1 needs fill (stream 0) and gemm1 (s2)
    cudaStreamWaitEvent(0, evB, 0);
    gather1_kernel<<<(n + 7) / 8, T>>>(b1, W2, n);
    gather2_kernel<<<(n + 7) / 8, T>>>(out, b2, n);
}